// round 16
// baseline (speedup 1.0000x reference)
#include <cuda_runtime.h>
#include <cuda_bf16.h>
#include <cstdint>
#include <math.h>

#define NN   500
#define DEG  16
#define BB   8
#define TT   12
#define HH   64
#define FF   32
#define EE   (NN*DEG)      // 8000
#define BT   (BB*TT)       // 96
#define M1C  16
#define M2C  2
#define DOUT (2*HH*HH)     // 8192
#define PLANE (BT*HH)      // 6144
#define LOG2E 1.4426950408889634f

// k2bf smem layout (dynamic): A splits then W splits, SW128-swizzled 128B rows
#define A_SPL 12288                    // 96 rows x 64 bf16 x 2B
#define W_SPL 32768                    // 256 rows x 64 bf16 x 2B
#define SM_A  0
#define SM_W  (3*A_SPL)                // 36864
#define K2_SMEM (SM_W + 3*W_SPL)       // 135168

// Static scratch (allocation-free)
__device__ int            g_bias_nz;
__device__ float          g_c[EE*2];                  // per-edge (c0,c1)
__device__ __nv_bfloat16  g_Wsplit[3*256*HH];         // [split][c][k] pre-split W
__device__ float          g_A[(size_t)NN*PLANE*2];    // src planes [n][m][bt][h]
__device__ float          g_B[(size_t)NN*PLANE*2];    // dst planes [n][m][bt][h]
__device__ float          g_Az[(size_t)NN*PLANE];     // bias planes (cold)
__device__ float          g_Bz[(size_t)NN*PLANE];

typedef unsigned long long ull;

// ---- helpers --------------------------------------------------------------
__device__ __forceinline__ uint32_t smem_u32(const void* p) {
    uint32_t a;
    asm("{ .reg .u64 t; cvta.to.shared.u64 t, %1; cvt.u32.u64 %0, t; }"
        : "=r"(a) : "l"(p));
    return a;
}
__device__ __forceinline__ float sigmoidf_(float x) {
    return __fdividef(1.0f, 1.0f + __expf(-x));
}
__device__ __forceinline__ ull dup2(float x) {
    ull r; asm("mov.b64 %0, {%1, %1};" : "=l"(r) : "r"(__float_as_uint(x))); return r;
}
__device__ __forceinline__ ull add2(ull a, ull b) {
    ull r; asm("add.rn.f32x2 %0, %1, %2;" : "=l"(r) : "l"(a), "l"(b)); return r;
}
__device__ __forceinline__ ull mul2(ull a, ull b) {
    ull r; asm("mul.rn.f32x2 %0, %1, %2;" : "=l"(r) : "l"(a), "l"(b)); return r;
}
__device__ __forceinline__ ull fma2r(ull a, ull b, ull c) {
    ull r; asm("fma.rn.f32x2 %0, %1, %2, %3;" : "=l"(r) : "l"(a), "l"(b), "l"(c)); return r;
}
__device__ __forceinline__ void unpk2(ull v, float& lo, float& hi) {
    unsigned a, b;
    asm("mov.b64 {%0, %1}, %2;" : "=r"(a), "=r"(b) : "l"(v));
    lo = __uint_as_float(a); hi = __uint_as_float(b);
}
__device__ __forceinline__ ull pk2(float lo, float hi) {
    ull r;
    asm("mov.b64 %0, {%1, %2};" : "=l"(r) : "r"(__float_as_uint(lo)), "r"(__float_as_uint(hi)));
    return r;
}
__device__ __forceinline__ float ex2f(float x) {
    float r; asm("ex2.approx.f32 %0, %1;" : "=f"(r) : "f"(x)); return r;
}
__device__ __forceinline__ void split3(float x, __nv_bfloat16& h,
                                       __nv_bfloat16& m, __nv_bfloat16& l) {
    h = __float2bfloat16(x);
    float r1 = x - __bfloat162float(h);
    m = __float2bfloat16(r1);
    l = __float2bfloat16(r1 - __bfloat162float(m));
}

#define LDSM_X4(r0,r1,r2,r3,a) \
    asm volatile("ldmatrix.sync.aligned.m8n8.x4.shared.b16 {%0,%1,%2,%3}, [%4];" \
        : "=r"(r0),"=r"(r1),"=r"(r2),"=r"(r3) : "r"(a))
#define LDSM_X2(r0,r1,a) \
    asm volatile("ldmatrix.sync.aligned.m8n8.x2.shared.b16 {%0,%1}, [%2];" \
        : "=r"(r0),"=r"(r1) : "r"(a))
#define MMA_BF16(d,a,b) \
    asm volatile("mma.sync.aligned.m16n8k16.row.col.f32.bf16.bf16.f32 " \
        "{%0,%1,%2,%3}, {%4,%5,%6,%7}, {%8,%9}, {%0,%1,%2,%3};" \
        : "+f"((d)[0]),"+f"((d)[1]),"+f"((d)[2]),"+f"((d)[3]) \
        : "r"((a)[0]),"r"((a)[1]),"r"((a)[2]),"r"((a)[3]), "r"((b)[0]),"r"((b)[1]))

// ---------------------------------------------------------------------------
// kprep: 3-way bf16 split of W3 into g_Wsplit, + bias_nz. grid=64, block=256.
//   Wc cols c = pl*64+h, pl = hf*2+m (X0,X1,Y0,Y1); element (k,c) = W3[m][hf*64+k][h]
// ---------------------------------------------------------------------------
__global__ void __launch_bounds__(256) kprep(
        const float* __restrict__ W3,
        const float* __restrict__ b3) {
    int tid = threadIdx.x;
    if (blockIdx.x == 0) {
        int nz = 0;
        const float4* b4 = (const float4*)b3;
        for (int i = tid; i < DOUT/4; i += 256) {
            float4 v = __ldg(b4 + i);
            nz |= (v.x != 0.f) | (v.y != 0.f) | (v.z != 0.f) | (v.w != 0.f);
        }
        nz = __syncthreads_or(nz);
        if (tid == 0) g_bias_nz = nz;
    }
    int i = blockIdx.x*256 + tid;          // 0..16383, natural W3 order
    int h  = i & 63;
    int k  = (i >> 6) & 63;
    int hf = (i >> 12) & 1;
    int m  = i >> 13;
    float v = __ldg(W3 + i);
    int c = (hf*2 + m)*HH + h;
    __nv_bfloat16 bh, bm, bl;
    split3(v, bh, bm, bl);
    g_Wsplit[0*16384 + c*HH + k] = bh;
    g_Wsplit[1*16384 + c*HH + k] = bm;
    g_Wsplit[2*16384 + c*HH + k] = bl;
}

// ---------------------------------------------------------------------------
// k2bf: per-node projections via bf16 mma.sync (3-way compensated split).
//   grid = N, block = 192 (6 warps; warp w owns m-tile rows w*16..w*16+15).
//   P[96,256] = s[96,64] @ Wc[64,256]; cols [X0|X1|Y0|Y1] -> g_A/g_B planes.
//   Also: edge hypernetwork (128 thr), cold bias planes if b3 != 0.
// ---------------------------------------------------------------------------
__global__ void __launch_bounds__(192) k2bf(
        const float* __restrict__ state,
        const float* __restrict__ feature,
        const float* __restrict__ dist,
        const float* __restrict__ W1,
        const float* __restrict__ b1,
        const float* __restrict__ W2,
        const float* __restrict__ b2,
        const float* __restrict__ b3,
        const int*   __restrict__ src,
        const int*   __restrict__ dst) {
    extern __shared__ char smc[];
    uint32_t smb = smem_u32(smc);
    int n = blockIdx.x, tid = threadIdx.x;
    int w = tid >> 5, lane = tid & 31;
    int nz = g_bias_nz;

    // ---- A conversion: s[n] -> 3 bf16 splits, SW128 rows ----
    for (int i = tid; i < 3072; i += 192) {
        int row = i >> 5, c2 = (i & 31) * 2;
        float2 v = *(const float2*)(state + ((size_t)row*NN + n)*HH + c2);
        __nv_bfloat16 h0,m0,l0, h1,m1,l1;
        split3(v.x, h0, m0, l0);
        split3(v.y, h1, m1, l1);
        uint32_t off = (uint32_t)(row*128 + c2*2);
        uint32_t sw  = off ^ (((off >> 3) & 0x70));
        __nv_bfloat162 t;
        t.x=h0; t.y=h1; *(__nv_bfloat162*)(smc + SM_A + sw)            = t;
        t.x=m0; t.y=m1; *(__nv_bfloat162*)(smc + SM_A + A_SPL + sw)    = t;
        t.x=l0; t.y=l1; *(__nv_bfloat162*)(smc + SM_A + 2*A_SPL + sw)  = t;
    }
    // ---- W copy: pre-split gmem -> swizzled smem (16B chunks) ----
    for (int i = tid; i < 6144; i += 192) {
        int s = i >> 11;                 // 2048 chunks per split
        int j = i & 2047;
        int c = j >> 3, kb = (j & 7) * 16;
        float4 v = __ldg((const float4*)((const char*)g_Wsplit + s*W_SPL + c*128 + kb));
        uint32_t off = (uint32_t)(c*128 + kb);
        uint32_t sw  = off ^ (((off >> 3) & 0x70));
        *(float4*)(smc + SM_W + s*W_SPL + sw) = v;
    }

    // ---- edge hypernetwork: 128 threads, 16 edges x 8 unit-pairs ----
    if (tid < 128) {
        int e  = n*DEG + (tid >> 3);
        int m2 = (tid & 7) * 2;
        int se = __ldg(src + e);
        int de = __ldg(dst + e);
        float dd = __ldg(dist + e);
        float z0 = __ldg(b1 + m2)     + dd * __ldg(W1 + 2*FF*M1C + m2);
        float z1 = __ldg(b1 + m2 + 1) + dd * __ldg(W1 + 2*FF*M1C + m2 + 1);
        const float* fs = feature + se*FF;
        const float* fd = feature + de*FF;
        #pragma unroll 8
        for (int i = 0; i < FF; i++) {
            float f1 = __ldg(fs + i), f2 = __ldg(fd + i);
            z0 = fmaf(f1, __ldg(W1 + i*M1C + m2), z0);
            z0 = fmaf(f2, __ldg(W1 + (FF+i)*M1C + m2), z0);
            z1 = fmaf(f1, __ldg(W1 + i*M1C + m2 + 1), z1);
            z1 = fmaf(f2, __ldg(W1 + (FF+i)*M1C + m2 + 1), z1);
        }
        float h0 = sigmoidf_(z0), h1 = sigmoidf_(z1);
        float p0 = h0*__ldg(W2 + m2*M2C) + h1*__ldg(W2 + (m2+1)*M2C);
        float p1 = h0*__ldg(W2 + m2*M2C + 1) + h1*__ldg(W2 + (m2+1)*M2C + 1);
        #pragma unroll
        for (int mk = 1; mk < 8; mk <<= 1) {
            p0 += __shfl_xor_sync(0xFFFFFFFFu, p0, mk);
            p1 += __shfl_xor_sync(0xFFFFFFFFu, p1, mk);
        }
        if ((tid & 7) == 0) {
            g_c[e*2 + 0] = sigmoidf_(p0 + __ldg(b2 + 0));
            g_c[e*2 + 1] = sigmoidf_(p1 + __ldg(b2 + 1));
        }
    }
    __syncthreads();

    // ---- tensor GEMM: warp w = m-tile w ----
    int l8   = lane & 7;
    int quad = lane >> 3;
    int rloc = l8 + ((quad & 1) << 3);
    int kadd = (quad >> 1) << 4;
    uint32_t aXor = (uint32_t)(l8 << 4);
    int bsel = quad & 1;                 // x2 matrix select for B

    uint32_t af[4][3][4];
    #pragma unroll
    for (int ks = 0; ks < 4; ks++)
        #pragma unroll
        for (int s = 0; s < 3; s++) {
            uint32_t addr = smb + SM_A + s*A_SPL + (uint32_t)((w*16 + rloc)*128)
                          + (((uint32_t)(ks*32 + kadd)) ^ aXor);
            LDSM_X4(af[ks][s][0], af[ks][s][1], af[ks][s][2], af[ks][s][3], addr);
        }

    #pragma unroll
    for (int p = 0; p < 2; p++) {
        #pragma unroll
        for (int nt = 0; nt < 16; nt++) {
            int c0 = p*128 + nt*8;
            float acc[4] = {0.f, 0.f, 0.f, 0.f};
            #pragma unroll
            for (int ks = 0; ks < 4; ks++) {
                uint32_t bf[3][2];
                #pragma unroll
                for (int s = 0; s < 3; s++) {
                    uint32_t addr = smb + SM_W + s*W_SPL
                                  + (uint32_t)((c0 + l8)*128)
                                  + (((uint32_t)(ks*32 + (bsel << 4))) ^ aXor);
                    LDSM_X2(bf[s][0], bf[s][1], addr);
                }
                MMA_BF16(acc, af[ks][0], bf[0]);
                MMA_BF16(acc, af[ks][0], bf[1]);
                MMA_BF16(acc, af[ks][1], bf[0]);
                MMA_BF16(acc, af[ks][0], bf[2]);
                MMA_BF16(acc, af[ks][1], bf[1]);
                MMA_BF16(acc, af[ks][2], bf[0]);
            }
            int pl = c0 >> 6;
            int h  = (c0 & 63) + (lane & 3)*2;
            int bt = w*16 + (lane >> 2);
            float* plane = (pl < 2)
                ? g_A + (size_t)n*PLANE*2 + (size_t)pl*PLANE
                : g_B + (size_t)n*PLANE*2 + (size_t)(pl - 2)*PLANE;
            *(float2*)(plane + bt*HH + h)     = make_float2(acc[0], acc[1]);
            *(float2*)(plane + (bt+8)*HH + h) = make_float2(acc[2], acc[3]);
        }
    }

    // ---- cold bias planes (general correctness; dataset b3 == 0) ----
    if (nz) {
        for (int idx = tid; idx < 2*PLANE; idx += 192) {
            int which = idx >= PLANE;
            int pp = idx - which*PLANE;
            int bt = pp >> 6, h = pp & 63;
            const float* sp = state + ((size_t)bt*NN + n)*HH;
            float a = 0.f;
            #pragma unroll 8
            for (int k = 0; k < HH; k++)
                a = fmaf(sp[k], __ldg(b3 + (which*HH + k)*HH + h), a);
            (which ? g_Bz : g_Az)[(size_t)n*PLANE + pp] = a;
        }
    }
}

// ---------------------------------------------------------------------------
// K3: combine + single-pass softmax + aggregate. grid = N*6 bt-tiles.
// (round-14 packed version, measured 39.9us)
// ---------------------------------------------------------------------------
__global__ void __launch_bounds__(256, 4) k3_combine(
        const float* __restrict__ state,
        const float* __restrict__ gate,
        const int*   __restrict__ src,
        const int*   __restrict__ dst,
        float*       __restrict__ out) {
    int n    = blockIdx.x / 6;
    int tile = blockIdx.x % 6;

    __shared__ ull  c0d[DEG], c1d[DEG];
    __shared__ int  srcs[DEG];
    __shared__ int  dstn_s;
    int tid = threadIdx.x;
    if (tid < DEG) {
        int e = n*DEG + tid;
        srcs[tid] = src[e];
        c0d[tid]  = dup2(g_c[e*2 + 0] * LOG2E);
        c1d[tid]  = dup2(g_c[e*2 + 1] * LOG2E);
        if (tid == 0) dstn_s = dst[n*DEG];
    }
    int bias_nz = g_bias_nz;
    __syncthreads();

    int dstn = dstn_s;
    int h4   = (tid & 15) * 4;
    int bt   = tile*16 + (tid >> 4);
    size_t eoff = (size_t)bt*HH + h4;

    const float* yp = g_B + (size_t)dstn*PLANE*2 + eoff;
    ulonglong2 y0 = *(const ulonglong2*)(yp);
    ulonglong2 y1 = *(const ulonglong2*)(yp + PLANE);

    const float* xbase  = g_A + eoff;
    const float* stbase = state + (size_t)bt*NN*HH + h4;

    ull numA = 0ull, numB = 0ull, denA = 0ull, denB = 0ull;

    if (!bias_nz) {
        #pragma unroll
        for (int j = 0; j < DEG; j++) {
            int sj = srcs[j];
            const float* xp = xbase + (size_t)sj*(PLANE*2);
            ulonglong2 x0 = *(const ulonglong2*)(xp);
            ulonglong2 x1 = *(const ulonglong2*)(xp + PLANE);
            ulonglong2 s4 = *(const ulonglong2*)(stbase + (size_t)sj*HH);
            ull c0 = c0d[j], c1 = c1d[j];
            ull aA = fma2r(c0, add2(x0.x, y0.x), mul2(c1, add2(x1.x, y1.x)));
            ull aB = fma2r(c0, add2(x0.y, y0.y), mul2(c1, add2(x1.y, y1.y)));
            float a0, a1, a2, a3;
            unpk2(aA, a0, a1);
            unpk2(aB, a2, a3);
            a0 = fmaxf(a0, 0.01f*a0);
            a1 = fmaxf(a1, 0.01f*a1);
            a2 = fmaxf(a2, 0.01f*a2);
            a3 = fmaxf(a3, 0.01f*a3);
            float p0 = ex2f(a0), p1 = ex2f(a1), p2 = ex2f(a2), p3 = ex2f(a3);
            ull pA = pk2(p0, p1), pB = pk2(p2, p3);
            denA = add2(denA, pA);
            denB = add2(denB, pB);
            numA = fma2r(pA, s4.x, numA);
            numB = fma2r(pB, s4.y, numB);
        }
    } else {
        const ull L2 = dup2(LOG2E);
        ulonglong2 y2 = *(const ulonglong2*)(g_Bz + (size_t)dstn*PLANE + eoff);
        #pragma unroll
        for (int j = 0; j < DEG; j++) {
            int sj = srcs[j];
            const float* xp = xbase + (size_t)sj*(PLANE*2);
            ulonglong2 x0 = *(const ulonglong2*)(xp);
            ulonglong2 x1 = *(const ulonglong2*)(xp + PLANE);
            ulonglong2 x2 = *(const ulonglong2*)(g_Az + (size_t)sj*PLANE + eoff);
            ulonglong2 s4 = *(const ulonglong2*)(stbase + (size_t)sj*HH);
            ull c0 = c0d[j], c1 = c1d[j];
            ull bA = fma2r(L2, add2(x2.x, y2.x), mul2(c1, add2(x1.x, y1.x)));
            ull bB = fma2r(L2, add2(x2.y, y2.y), mul2(c1, add2(x1.y, y1.y)));
            ull aA = fma2r(c0, add2(x0.x, y0.x), bA);
            ull aB = fma2r(c0, add2(x0.y, y0.y), bB);
            float a0, a1, a2, a3;
            unpk2(aA, a0, a1);
            unpk2(aB, a2, a3);
            a0 = fmaxf(a0, 0.01f*a0);
            a1 = fmaxf(a1, 0.01f*a1);
            a2 = fmaxf(a2, 0.01f*a2);
            a3 = fmaxf(a3, 0.01f*a3);
            float p0 = ex2f(a0), p1 = ex2f(a1), p2 = ex2f(a2), p3 = ex2f(a3);
            ull pA = pk2(p0, p1), pB = pk2(p2, p3);
            denA = add2(denA, pA);
            denB = add2(denB, pB);
            numA = fma2r(pA, s4.x, numA);
            numB = fma2r(pB, s4.y, numB);
        }
    }

    float sg = sigmoidf_(gate[0]);
    float n0, n1, n2, n3, d0, d1, d2, d3;
    unpk2(numA, n0, n1);
    unpk2(numB, n2, n3);
    unpk2(denA, d0, d1);
    unpk2(denB, d2, d3);
    float4 o;
    o.x = fmaxf(__fdividef(n0, d0), 0.f) * sg;
    o.y = fmaxf(__fdividef(n1, d1), 0.f) * sg;
    o.z = fmaxf(__fdividef(n2, d2), 0.f) * sg;
    o.w = fmaxf(__fdividef(n3, d3), 0.f) * sg;
    *(float4*)(out + ((size_t)bt*NN + n)*HH + h4) = o;
}

// ---------------------------------------------------------------------------
extern "C" void kernel_launch(void* const* d_in, const int* in_sizes, int n_in,
                              void* d_out, int out_size) {
    const float* state   = (const float*)d_in[0];
    const float* feature = (const float*)d_in[1];
    const float* dist    = (const float*)d_in[2];
    const float* W1      = (const float*)d_in[3];
    const float* b1      = (const float*)d_in[4];
    const float* W2      = (const float*)d_in[5];
    const float* b2      = (const float*)d_in[6];
    const float* W3      = (const float*)d_in[7];
    const float* b3      = (const float*)d_in[8];
    const float* gate    = (const float*)d_in[9];
    const int*   src     = (const int*)d_in[10];
    const int*   dst     = (const int*)d_in[11];
    float* out = (float*)d_out;

    // 132KB dynamic smem opt-in (capture-safe; proven in round 7).
    (void)cudaFuncSetAttribute((const void*)k2bf,
                               cudaFuncAttributeMaxDynamicSharedMemorySize,
                               K2_SMEM);

    kprep<<<64, 256>>>(W3, b3);
    k2bf<<<NN, 192, K2_SMEM>>>(state, feature, dist, W1, b1, W2, b2, b3,
                               src, dst);
    k3_combine<<<NN*6, 256>>>(state, gate, src, dst, out);
}

// round 17
// speedup vs baseline: 1.1816x; 1.1816x over previous
#include <cuda_runtime.h>
#include <cstdint>
#include <math.h>

#define NN   500
#define DEG  16
#define BB   8
#define TT   12
#define HH   64
#define FF   32
#define EE   (NN*DEG)      // 8000
#define BT   (BB*TT)       // 96
#define M1C  16
#define M2C  2
#define DOUT (2*HH*HH)     // 8192
#define PLANE (BT*HH)      // 6144
#define LOG2E 1.4426950408889634f

// K2 dynamic smem: s_sm [96][64] + w_sm [64][128]
#define K2_SMEM ((BT*HH + HH*128)*4)    // 57344 B

// Static scratch (allocation-free)
__device__ int   g_bias_nz;
__device__ float g_c[EE*2];                  // per-edge (c0,c1)
__device__ float g_A[(size_t)NN*PLANE*2];    // src planes [n][m][bt][h]
__device__ float g_B[(size_t)NN*PLANE*2];    // dst planes [n][m][bt][h]
__device__ float g_Az[(size_t)NN*PLANE];     // bias planes (cold path)
__device__ float g_Bz[(size_t)NN*PLANE];

typedef unsigned long long ull;

__device__ __forceinline__ ull dup2(float x) {
    ull r; asm("mov.b64 %0, {%1, %1};" : "=l"(r) : "r"(__float_as_uint(x))); return r;
}
__device__ __forceinline__ void ffma2(ull& d, ull a, ull b) {
    asm("fma.rn.f32x2 %0, %1, %2, %3;" : "=l"(d) : "l"(a), "l"(b), "l"(d));
}
__device__ __forceinline__ ull add2(ull a, ull b) {
    ull r; asm("add.rn.f32x2 %0, %1, %2;" : "=l"(r) : "l"(a), "l"(b)); return r;
}
__device__ __forceinline__ ull mul2(ull a, ull b) {
    ull r; asm("mul.rn.f32x2 %0, %1, %2;" : "=l"(r) : "l"(a), "l"(b)); return r;
}
__device__ __forceinline__ ull fma2r(ull a, ull b, ull c) {
    ull r; asm("fma.rn.f32x2 %0, %1, %2, %3;" : "=l"(r) : "l"(a), "l"(b), "l"(c)); return r;
}
__device__ __forceinline__ void unpk2(ull v, float& lo, float& hi) {
    unsigned a, b;
    asm("mov.b64 {%0, %1}, %2;" : "=r"(a), "=r"(b) : "l"(v));
    lo = __uint_as_float(a); hi = __uint_as_float(b);
}
__device__ __forceinline__ ull pk2(float lo, float hi) {
    ull r;
    asm("mov.b64 %0, {%1, %2};" : "=l"(r) : "r"(__float_as_uint(lo)), "r"(__float_as_uint(hi)));
    return r;
}
__device__ __forceinline__ float ex2f(float x) {
    float r; asm("ex2.approx.f32 %0, %1;" : "=f"(r) : "f"(x)); return r;
}
__device__ __forceinline__ float sigmoidf_(float x) {
    return __fdividef(1.0f, 1.0f + __expf(-x));
}

// ---------------------------------------------------------------------------
// K2: per-(node, side) projections, BOTH m-planes in one fused GEMM pass.
// grid = 2N, block = 256, dynamic smem 57.3KB.
//   side 0 -> g_A (+g_c edge coefs), side 1 -> g_B. Bias planes: cold extra pass.
// ---------------------------------------------------------------------------
__global__ void __launch_bounds__(256) k2_precompute(
        const float* __restrict__ state,
        const float* __restrict__ feature,
        const float* __restrict__ dist,
        const float* __restrict__ W1,
        const float* __restrict__ b1,
        const float* __restrict__ W2,
        const float* __restrict__ b2,
        const float* __restrict__ W3,
        const float* __restrict__ b3,
        const int*   __restrict__ src,
        const int*   __restrict__ dst) {
    extern __shared__ float sm[];
    float* s_sm = sm;            // [96][64] (pitch 64: all GEMM reads are
    float* w_sm = sm + BT*HH;    // [64][128]  16-lane broadcasts, no conflicts)
    int bid  = blockIdx.x;
    int n    = bid >> 1;
    int side = bid & 1;
    int tid  = threadIdx.x;

    // bias-nonzero scan (b3 = 32KB, L2-resident; hidden under the FMA phase)
    int nz = 0;
    {
        const float4* b4 = (const float4*)b3;
        for (int i = tid; i < DOUT/4; i += 256) {
            float4 v = __ldg(b4 + i);
            nz |= (v.x != 0.f) | (v.y != 0.f) | (v.z != 0.f) | (v.w != 0.f);
        }
    }
    nz = __syncthreads_or(nz);
    if (tid == 0 && bid == 0) g_bias_nz = nz;

    // load s[n] (node-major view of state[B,T,N,H])
    for (int idx = tid; idx < BT*HH; idx += 256) {
        int bt = idx >> 6, h = idx & 63;
        s_sm[idx] = state[((size_t)bt*NN + n)*HH + h];
    }
    // load both W matrices: w_sm[k][m*64 + h] = W3[m][side*64 + k][h]
    for (int idx = tid; idx < HH*128; idx += 256) {
        int k = idx >> 7, c = idx & 127;
        int m = c >> 6, h = c & 63;
        w_sm[idx] = __ldg(W3 + (size_t)m*DOUT + (side*HH + k)*HH + h);
    }

    // side 0: per-edge hypernetwork for segment n (thread = (edge, unit))
    if (side == 0) {
        int el = tid >> 4;
        int m  = tid & 15;
        int e  = n*DEG + el;
        int se = __ldg(src + e);
        int de = __ldg(dst + e);
        float z = __ldg(b1 + m) + __ldg(dist + e) * __ldg(W1 + 2*FF*M1C + m);
        const float* fs = feature + se*FF;
        const float* fd = feature + de*FF;
        #pragma unroll 8
        for (int i = 0; i < FF; i++) {
            z = fmaf(__ldg(fs + i), __ldg(W1 + i*M1C + m), z);
            z = fmaf(__ldg(fd + i), __ldg(W1 + (FF+i)*M1C + m), z);
        }
        float h1 = sigmoidf_(z);
        float p0 = h1 * __ldg(W2 + m*M2C + 0);
        float p1 = h1 * __ldg(W2 + m*M2C + 1);
        #pragma unroll
        for (int mk = 1; mk < 16; mk <<= 1) {
            p0 += __shfl_xor_sync(0xFFFFFFFFu, p0, mk);
            p1 += __shfl_xor_sync(0xFFFFFFFFu, p1, mk);
        }
        if (m == 0) {
            g_c[e*2 + 0] = sigmoidf_(p0 + __ldg(b2 + 0));
            g_c[e*2 + 1] = sigmoidf_(p1 + __ldg(b2 + 1));
        }
    }
    __syncthreads();

    int c4 = (tid & 15) * 4;     // output cols c4..c4+3
    int ty = tid >> 4;           // rows ty, ty+16, ..., ty+80

    ull a0[6][2], a1[6][2];
    #pragma unroll
    for (int r = 0; r < 6; r++) {
        a0[r][0] = a0[r][1] = 0ull;
        a1[r][0] = a1[r][1] = 0ull;
    }

    #pragma unroll 4
    for (int k4 = 0; k4 < 16; k4++) {
        float4 sv[6];
        #pragma unroll
        for (int r = 0; r < 6; r++)
            sv[r] = *(const float4*)&s_sm[(ty + 16*r)*HH + k4*4];
        #pragma unroll
        for (int kk = 0; kk < 4; kk++) {
            int k = k4*4 + kk;
            ulonglong2 w0 = *(const ulonglong2*)&w_sm[k*128 + c4];
            ulonglong2 w1 = *(const ulonglong2*)&w_sm[k*128 + 64 + c4];
            #pragma unroll
            for (int r = 0; r < 6; r++) {
                float sval = (kk == 0) ? sv[r].x : (kk == 1) ? sv[r].y
                           : (kk == 2) ? sv[r].z : sv[r].w;
                ull sd = dup2(sval);
                ffma2(a0[r][0], w0.x, sd);
                ffma2(a0[r][1], w0.y, sd);
                ffma2(a1[r][0], w1.x, sd);
                ffma2(a1[r][1], w1.y, sd);
            }
        }
    }

    // stores: plane 0 (m0) and plane 1 (m1), coalesced float4 rows
    {
        float* outp = (side ? g_B : g_A) + (size_t)n*PLANE*2;
        #pragma unroll
        for (int r = 0; r < 6; r++) {
            int row = ty + 16*r;
            float4 v0, v1;
            unpk2(a0[r][0], v0.x, v0.y);
            unpk2(a0[r][1], v0.z, v0.w);
            unpk2(a1[r][0], v1.x, v1.y);
            unpk2(a1[r][1], v1.z, v1.w);
            size_t base = (size_t)row*HH + c4;
            *(float4*)(outp + base)         = v0;
            *(float4*)(outp + PLANE + base) = v1;
        }
    }

    // bias plane (cold path, general correctness; dataset b3 == 0)
    if (nz) {
        __syncthreads();   // everyone done reading w_sm
        for (int idx = tid; idx < HH*HH; idx += 256) {
            int k = idx >> 6, h = idx & 63;
            w_sm[k*128 + h] = __ldg(b3 + (side*HH + k)*HH + h);
        }
        __syncthreads();
        ull az[6][2];
        #pragma unroll
        for (int r = 0; r < 6; r++) { az[r][0] = 0ull; az[r][1] = 0ull; }
        #pragma unroll 4
        for (int k4 = 0; k4 < 16; k4++) {
            float4 sv[6];
            #pragma unroll
            for (int r = 0; r < 6; r++)
                sv[r] = *(const float4*)&s_sm[(ty + 16*r)*HH + k4*4];
            #pragma unroll
            for (int kk = 0; kk < 4; kk++) {
                int k = k4*4 + kk;
                ulonglong2 wz = *(const ulonglong2*)&w_sm[k*128 + c4];
                #pragma unroll
                for (int r = 0; r < 6; r++) {
                    float sval = (kk == 0) ? sv[r].x : (kk == 1) ? sv[r].y
                               : (kk == 2) ? sv[r].z : sv[r].w;
                    ull sd = dup2(sval);
                    ffma2(az[r][0], wz.x, sd);
                    ffma2(az[r][1], wz.y, sd);
                }
            }
        }
        float* outp = (side ? g_Bz : g_Az) + (size_t)n*PLANE;
        #pragma unroll
        for (int r = 0; r < 6; r++) {
            int row = ty + 16*r;
            float4 v;
            unpk2(az[r][0], v.x, v.y);
            unpk2(az[r][1], v.z, v.w);
            *(float4*)(outp + row*HH + c4) = v;
        }
    }
}

// ---------------------------------------------------------------------------
// K3: combine + single-pass softmax + aggregate. grid = N*6.
// TILE-MAJOR block order: concurrent wave touches a ~1/5 slice of g_A/state
// (hot L2 set, cross-block L1 reuse on shared src rows).
// ---------------------------------------------------------------------------
__global__ void __launch_bounds__(256, 4) k3_combine(
        const float* __restrict__ state,
        const float* __restrict__ gate,
        const int*   __restrict__ src,
        const int*   __restrict__ dst,
        float*       __restrict__ out) {
    int tile = blockIdx.x / NN;      // 0..5  (tile-major)
    int n    = blockIdx.x % NN;

    __shared__ ull  c0d[DEG], c1d[DEG];
    __shared__ int  srcs[DEG];
    __shared__ int  dstn_s;
    int tid = threadIdx.x;
    if (tid < DEG) {
        int e = n*DEG + tid;
        srcs[tid] = src[e];
        c0d[tid]  = dup2(g_c[e*2 + 0] * LOG2E);
        c1d[tid]  = dup2(g_c[e*2 + 1] * LOG2E);
        if (tid == 0) dstn_s = dst[n*DEG];
    }
    int bias_nz = g_bias_nz;
    __syncthreads();

    int dstn = dstn_s;
    int h4   = (tid & 15) * 4;
    int bt   = tile*16 + (tid >> 4);
    size_t eoff = (size_t)bt*HH + h4;

    const float* yp = g_B + (size_t)dstn*PLANE*2 + eoff;
    ulonglong2 y0 = *(const ulonglong2*)(yp);
    ulonglong2 y1 = *(const ulonglong2*)(yp + PLANE);

    const float* xbase  = g_A + eoff;
    const float* stbase = state + (size_t)bt*NN*HH + h4;

    ull numA = 0ull, numB = 0ull, denA = 0ull, denB = 0ull;

    if (!bias_nz) {
        #pragma unroll
        for (int j = 0; j < DEG; j++) {
            int sj = srcs[j];
            const float* xp = xbase + (size_t)sj*(PLANE*2);
            ulonglong2 x0 = *(const ulonglong2*)(xp);
            ulonglong2 x1 = *(const ulonglong2*)(xp + PLANE);
            ulonglong2 s4 = *(const ulonglong2*)(stbase + (size_t)sj*HH);
            ull c0 = c0d[j], c1 = c1d[j];
            ull aA = fma2r(c0, add2(x0.x, y0.x), mul2(c1, add2(x1.x, y1.x)));
            ull aB = fma2r(c0, add2(x0.y, y0.y), mul2(c1, add2(x1.y, y1.y)));
            float a0, a1, a2, a3;
            unpk2(aA, a0, a1);
            unpk2(aB, a2, a3);
            a0 = fmaxf(a0, 0.01f*a0);
            a1 = fmaxf(a1, 0.01f*a1);
            a2 = fmaxf(a2, 0.01f*a2);
            a3 = fmaxf(a3, 0.01f*a3);
            float p0 = ex2f(a0), p1 = ex2f(a1), p2 = ex2f(a2), p3 = ex2f(a3);
            ull pA = pk2(p0, p1), pB = pk2(p2, p3);
            denA = add2(denA, pA);
            denB = add2(denB, pB);
            numA = fma2r(pA, s4.x, numA);
            numB = fma2r(pB, s4.y, numB);
        }
    } else {
        const ull L2 = dup2(LOG2E);
        ulonglong2 y2 = *(const ulonglong2*)(g_Bz + (size_t)dstn*PLANE + eoff);
        #pragma unroll
        for (int j = 0; j < DEG; j++) {
            int sj = srcs[j];
            const float* xp = xbase + (size_t)sj*(PLANE*2);
            ulonglong2 x0 = *(const ulonglong2*)(xp);
            ulonglong2 x1 = *(const ulonglong2*)(xp + PLANE);
            ulonglong2 x2 = *(const ulonglong2*)(g_Az + (size_t)sj*PLANE + eoff);
            ulonglong2 s4 = *(const ulonglong2*)(stbase + (size_t)sj*HH);
            ull c0 = c0d[j], c1 = c1d[j];
            ull bA = fma2r(L2, add2(x2.x, y2.x), mul2(c1, add2(x1.x, y1.x)));
            ull bB = fma2r(L2, add2(x2.y, y2.y), mul2(c1, add2(x1.y, y1.y)));
            ull aA = fma2r(c0, add2(x0.x, y0.x), bA);
            ull aB = fma2r(c0, add2(x0.y, y0.y), bB);
            float a0, a1, a2, a3;
            unpk2(aA, a0, a1);
            unpk2(aB, a2, a3);
            a0 = fmaxf(a0, 0.01f*a0);
            a1 = fmaxf(a1, 0.01f*a1);
            a2 = fmaxf(a2, 0.01f*a2);
            a3 = fmaxf(a3, 0.01f*a3);
            float p0 = ex2f(a0), p1 = ex2f(a1), p2 = ex2f(a2), p3 = ex2f(a3);
            ull pA = pk2(p0, p1), pB = pk2(p2, p3);
            denA = add2(denA, pA);
            denB = add2(denB, pB);
            numA = fma2r(pA, s4.x, numA);
            numB = fma2r(pB, s4.y, numB);
        }
    }

    float sg = sigmoidf_(gate[0]);
    float n0, n1, n2, n3, d0, d1, d2, d3;
    unpk2(numA, n0, n1);
    unpk2(numB, n2, n3);
    unpk2(denA, d0, d1);
    unpk2(denB, d2, d3);
    float4 o;
    o.x = fmaxf(__fdividef(n0, d0), 0.f) * sg;
    o.y = fmaxf(__fdividef(n1, d1), 0.f) * sg;
    o.z = fmaxf(__fdividef(n2, d2), 0.f) * sg;
    o.w = fmaxf(__fdividef(n3, d3), 0.f) * sg;
    *(float4*)(out + ((size_t)bt*NN + n)*HH + h4) = o;
}

// ---------------------------------------------------------------------------
extern "C" void kernel_launch(void* const* d_in, const int* in_sizes, int n_in,
                              void* d_out, int out_size) {
    const float* state   = (const float*)d_in[0];
    const float* feature = (const float*)d_in[1];
    const float* dist    = (const float*)d_in[2];
    const float* W1      = (const float*)d_in[3];
    const float* b1      = (const float*)d_in[4];
    const float* W2      = (const float*)d_in[5];
    const float* b2      = (const float*)d_in[6];
    const float* W3      = (const float*)d_in[7];
    const float* b3      = (const float*)d_in[8];
    const float* gate    = (const float*)d_in[9];
    const int*   src     = (const int*)d_in[10];
    const int*   dst     = (const int*)d_in[11];
    float* out = (float*)d_out;

    // 57.3KB dynamic smem opt-in (capture-safe; proven in round 7).
    (void)cudaFuncSetAttribute((const void*)k2_precompute,
                               cudaFuncAttributeMaxDynamicSharedMemorySize,
                               K2_SMEM);

    k2_precompute<<<NN*2, 256, K2_SMEM>>>(state, feature, dist, W1, b1, W2, b2,
                                          W3, b3, src, dst);
    k3_combine<<<NN*6, 256>>>(state, gate, src, dst, out);
}